// round 16
// baseline (speedup 1.0000x reference)
#include <cuda_runtime.h>
#include <cuda_bf16.h>
#include <cstdint>

// NCEAverage: B=256, D=128, N=1e6, K1=2048, T=0.07, MOMENTUM=0.5
// Output: [ out_l(B*K1) | out_ab(B*K1) | new_memory_l(N*D) | new_memory_ab(N*D) ]
//
// R16 = R15 with (a) one-wave grid (1184 blocks, 592/half — exactly resident),
// (b) row-update folded into the stream via marker bits packed into g_count's
// high bits (word already prefetched; copy store stays unconditional+first;
// marked rows get a second store with the EMA value), (c) update kernel gone.
// g_count word: bits [0,20) = task count, bits [20,32) = last-occurrence b+1.

#define DIM      128
#define T_INV    (1.0f / 0.07f)
#define N_MAX    1048576
#define CAP      12
#define CNT_MASK 0xFFFFF

__device__ int g_count[N_MAX];
__device__ int g_tasks[N_MAX * CAP];
__device__ int g_ovf  [4096];
__device__ int g_novf;

// ---------------- build: bucket scatter ----------------
__global__ void k_scatter(const int* __restrict__ idx, int bk) {
    for (int t = blockIdx.x * blockDim.x + threadIdx.x; t < bk;
         t += gridDim.x * blockDim.x) {
        const int row  = idx[t];
        const int slot = atomicAdd(&g_count[row], 1);
        if (slot < CAP) g_tasks[row * CAP + slot] = t;
        else            g_ovf[atomicAdd(&g_novf, 1)] = t;
    }
}

// ---------------- mark updated rows (block 0) + overflow fixup (block 1) ----
__global__ void __launch_bounds__(256) k_mark(
    const int* __restrict__ y, const int* __restrict__ idx,
    const float* __restrict__ mem_l, const float* __restrict__ mem_ab,
    const float4* __restrict__ ql, const float4* __restrict__ qab,
    float* __restrict__ out_l, float* __restrict__ out_ab, int B, int K1)
{
    const int tid = threadIdx.x;

    if (blockIdx.x == 0) {
        __shared__ int ys[1024];
        for (int j = tid; j < B; j += 256) ys[j] = y[j];
        __syncthreads();
        if (tid < B) {
            const int yy = ys[tid];
            bool dup = false;
            for (int j = tid + 1; j < B; ++j) if (ys[j] == yy) { dup = true; break; }
            if (!dup) g_count[yy] += (tid + 1) << 20;   // unique row per thread
        }
        return;
    }

    // ---- overflow tasks (expected 0) ----
    const int n = g_novf;
    const int lane = tid & 31;
    for (int i = tid >> 5; i < n; i += 8) {
        const int task = g_ovf[i];
        const int b    = task / K1;
        const long long row = idx[task];
        const float4 wl  = ((const float4*)(mem_l  + row * DIM))[lane];
        const float4 wab = ((const float4*)(mem_ab + row * DIM))[lane];
        const float4 q1  = qab[b * 32 + lane];
        const float4 q2  = ql [b * 32 + lane];
        float s1 = wl.x * q1.x + wl.y * q1.y + wl.z * q1.z + wl.w * q1.w;
        float s2 = wab.x * q2.x + wab.y * q2.y + wab.z * q2.z + wab.w * q2.w;
        #pragma unroll
        for (int o = 16; o; o >>= 1) {
            s1 += __shfl_xor_sync(0xffffffffu, s1, o);
            s2 += __shfl_xor_sync(0xffffffffu, s2, o);
        }
        if (lane == 0) {
            out_ab[task] = s1 * T_INV;
            out_l [task] = s2 * T_INV;
        }
    }
}

// ---------------- dual streaming pass: copy + score + folded update ---------
__global__ void __launch_bounds__(256) stream_score_dual(
    const float4* __restrict__ bank_l, const float4* __restrict__ bank_ab,
    float4* __restrict__ out_ml, float4* __restrict__ out_mab,
    const float4* __restrict__ ql, const float4* __restrict__ qab,
    float* __restrict__ out_l, float* __restrict__ out_ab,
    int Nrows, int K1)
{
    const int halfG = gridDim.x >> 1;
    const bool second = (blockIdx.x >= (unsigned)halfG);
    const int  blk    = second ? (blockIdx.x - halfG) : blockIdx.x;

    const float4* __restrict__ bank  = second ? bank_ab : bank_l;
    float4*       __restrict__ outb  = second ? out_mab : out_ml;
    const float4* __restrict__ query = second ? ql      : qab;  // dotted vs bank
    const float4* __restrict__ updv  = second ? qab     : ql;   // EMA'd into bank
    float*        __restrict__ out_s = second ? out_l   : out_ab;

    const int lane = threadIdx.x & 31;
    const int nw   = halfG * (blockDim.x >> 5);
    int r          = blk * (blockDim.x >> 5) + (threadIdx.x >> 5);

    if (r >= Nrows) return;
    float4 v  = __ldcs(&bank[(long long)r * 32 + lane]);
    int    cw = g_count[r];

    while (true) {
        const int rn = r + nw;
        float4 vn;
        int    cn = 0;
        if (rn < Nrows) {                         // prefetch next row + count word
            vn = __ldcs(&bank[(long long)rn * 32 + lane]);
            cn = g_count[rn];
        }

        __stcs(&outb[(long long)r * 32 + lane], v);   // unconditional copy FIRST

        int cnt = cw & CNT_MASK;
        if (cnt) {
            if (cnt > CAP) cnt = CAP;
            const int base = r * CAP;
            for (int j = 0; j < cnt; ++j) {
                const int task = g_tasks[base + j];
                const int b    = task / K1;
                const float4 q = query[b * 32 + lane];
                float s = v.x * q.x + v.y * q.y + v.z * q.z + v.w * q.w;
                #pragma unroll
                for (int o = 16; o; o >>= 1) s += __shfl_xor_sync(0xffffffffu, s, o);
                if (lane == 0) out_s[task] = s * T_INV;
            }
        }

        const int ub = ((unsigned)cw) >> 20;          // last-occurrence b+1
        if (ub) {                                      // ~255 rows chip-wide
            const float4 u = updv[(ub - 1) * 32 + lane];
            float4 wv;
            wv.x = 0.5f * v.x + 0.5f * u.x;
            wv.y = 0.5f * v.y + 0.5f * u.y;
            wv.z = 0.5f * v.z + 0.5f * u.z;
            wv.w = 0.5f * v.w + 0.5f * u.w;
            float ss = wv.x * wv.x + wv.y * wv.y + wv.z * wv.z + wv.w * wv.w;
            #pragma unroll
            for (int o = 16; o; o >>= 1) ss += __shfl_xor_sync(0xffffffffu, ss, o);
            const float inv = rsqrtf(ss);
            wv.x *= inv; wv.y *= inv; wv.z *= inv; wv.w *= inv;
            __stcs(&outb[(long long)r * 32 + lane], wv);   // overwrite (same thread)
        }

        if (rn >= Nrows) break;
        r  = rn;
        v  = vn;
        cw = cn;
    }
}

extern "C" void kernel_launch(void* const* d_in, const int* in_sizes, int n_in,
                              void* d_out, int out_size)
{
    const float* l      = (const float*)d_in[0];
    const float* ab     = (const float*)d_in[1];
    const int*   y      = (const int*)  d_in[2];
    const int*   idx    = (const int*)  d_in[3];
    const float* mem_l  = (const float*)d_in[4];
    const float* mem_ab = (const float*)d_in[5];

    const int       B     = in_sizes[2];
    const int       BK    = in_sizes[3];
    const int       K1    = BK / B;
    const long long ND    = (long long)in_sizes[4];
    const int       Nrows = (int)(ND / DIM);

    float* out = (float*)d_out;
    float* out_l   = out;
    float* out_ab  = out + BK;
    float* out_ml  = out + 2LL * BK;
    float* out_mab = out + 2LL * BK + ND;

    // ---- reset metadata (no allocation; graph-capturable) ----
    void* p_count; cudaGetSymbolAddress(&p_count, g_count);
    void* p_novf;  cudaGetSymbolAddress(&p_novf,  g_novf);
    cudaMemsetAsync(p_count, 0, (size_t)Nrows * sizeof(int));
    cudaMemsetAsync(p_novf,  0, sizeof(int));

    // ---- build: row->task buckets, then mark updated rows + overflow ----
    k_scatter<<<512, 1024>>>(idx, BK);
    k_mark<<<2, 256>>>(y, idx, mem_l, mem_ab,
                       (const float4*)l, (const float4*)ab,
                       out_l, out_ab, B, K1);

    // ---- single one-wave pass: both banks, copy + score + folded update ----
    stream_score_dual<<<148 * 8, 256>>>(
        (const float4*)mem_l, (const float4*)mem_ab,
        (float4*)out_ml, (float4*)out_mab,
        (const float4*)l, (const float4*)ab,
        out_l, out_ab, Nrows, K1);
}